// round 11
// baseline (speedup 1.0000x reference)
#include <cuda_runtime.h>
#include <cuda_fp16.h>
#include <cstdint>

// ---------------- problem constants ----------------
#define M_TOTAL   4096
#define K_TOTAL   4096
#define N_TOTAL   11008

#define BM        128
#define BN        256
#define BK        64                  // fp16 per K chunk (128 B/row)
#define NKIT      (K_TOTAL / BK)      // 64
#define MT_TILES  (M_TOTAL / BM)      // 32
#define NT_TILES  (N_TOTAL / BN)      // 43
#define NTILES    (MT_TILES * NT_TILES)  // 1376
#define STAGES    4
#define NTHREADS  256

#define A_CHUNK_BYTES 16384                             // 128 rows x 128B, pre-swizzled
#define B_CHUNK_BYTES 32768                             // 256 rows x 128B, pre-swizzled
#define STAGE_BYTES   (A_CHUNK_BYTES + B_CHUNK_BYTES)   // 49152
#define SMEM_DATA     (STAGES * STAGE_BYTES)            // 196608
#define SMEM_MBAR     SMEM_DATA                         // full[4] then empty[4]
#define SMEM_BYTES    (SMEM_DATA + 80)

// ---------------- device scratch (tile-major, pre-swizzled) ----------------
static __device__ __align__(16) __half g_xh[(size_t)M_TOTAL * K_TOTAL];   // ~34 MB
static __device__ __align__(16) __half g_w [(size_t)N_TOTAL * K_TOTAL];   // ~90 MB
static __device__ int g_ctr;

// ---------------- helpers ----------------
#define SWZ(off) ((off) ^ (((off) >> 3) & 0x70))

__device__ __forceinline__ uint32_t smem_u32(const void* p) {
    uint32_t a;
    asm("{ .reg .u64 t; cvta.to.shared.u64 t, %1; cvt.u32.u64 %0, t; }" : "=r"(a) : "l"(p));
    return a;
}

#define CP_BULK(dst_u32, src_ptr, bytes, mbar_u32) \
    asm volatile("cp.async.bulk.shared::cluster.global.mbarrier::complete_tx::bytes " \
                 "[%0], [%1], %2, [%3];" \
                 :: "r"(dst_u32), "l"(src_ptr), "r"(bytes), "r"(mbar_u32) : "memory")

#define MBARRIER_INIT(mbar, cnt) \
    asm volatile("mbarrier.init.shared.b64 [%0], %1;" \
                 :: "r"((uint32_t)(mbar)), "r"((uint32_t)(cnt)) : "memory")
#define MBARRIER_EXPECT_TX(mbar, tx) \
    asm volatile("mbarrier.arrive.expect_tx.shared.b64 _, [%0], %1;" \
                 :: "r"((uint32_t)(mbar)), "r"((uint32_t)(tx)) : "memory")
#define MBARRIER_ARRIVE(mbar) \
    asm volatile("mbarrier.arrive.shared.b64 _, [%0];" \
                 :: "r"((uint32_t)(mbar)) : "memory")

#define MBARRIER_WAIT_PARITY(mbar_smem_addr, phase_parity) do { \
    uint32_t _mbar = (uint32_t)(mbar_smem_addr); \
    uint32_t _parity = (uint32_t)(phase_parity); \
    uint32_t _done; \
    asm volatile( \
        "{\n\t.reg .pred p;\n\t" \
        "mbarrier.try_wait.parity.acquire.cta.shared::cta.b64 p, [%1], %2;\n\t" \
        "selp.b32 %0, 1, 0, p;\n\t}" \
        : "=r"(_done) : "r"(_mbar), "r"(_parity) : "memory"); \
    if (!_done) { \
        asm volatile( \
            "{\n\t.reg .pred P1;\n\t" \
            "WAIT_LOOP_%=:\n\t" \
            "mbarrier.try_wait.parity.acquire.cta.shared::cta.b64 P1, [%0], %1, 0x989680;\n\t" \
            "@P1 bra.uni WAIT_DONE_%=;\n\t" \
            "bra.uni WAIT_LOOP_%=;\n\t" \
            "WAIT_DONE_%=:\n\t}" \
            :: "r"(_mbar), "r"(_parity) : "memory"); \
    } \
} while (0)

#define LDSM_X4(r0, r1, r2, r3, addr) \
    asm volatile("ldmatrix.sync.aligned.m8n8.x4.shared.b16 {%0,%1,%2,%3}, [%4];" \
                 : "=r"(r0), "=r"(r1), "=r"(r2), "=r"(r3) : "r"(addr))

#define MMA16816(c, a, b) \
    asm volatile("mma.sync.aligned.m16n8k16.row.col.f32.f16.f16.f32 " \
                 "{%0,%1,%2,%3}, {%4,%5,%6,%7}, {%8,%9}, {%0,%1,%2,%3};" \
                 : "+f"((c)[0]), "+f"((c)[1]), "+f"((c)[2]), "+f"((c)[3]) \
                 : "r"((a)[0]), "r"((a)[1]), "r"((a)[2]), "r"((a)[3]), \
                   "r"((b)[0]), "r"((b)[1]))

// ---------------- fused prep kernel: tile-major pre-swizzled outputs ----------------
// A: 16KB chunks of 128 rows;  W: 32KB chunks of 256 rows
__device__ __forceinline__ uint32_t dq_pair(int v) {
    int lo = (v & 15) - 8;
    int hi = ((v >> 4) & 15) - 8;
    __half2 h = __floats2half2_rn((float)lo, (float)hi);
    return *(uint32_t*)&h;
}

__global__ void k_prep(const float* __restrict__ x, const int* __restrict__ wp) {
    if (blockIdx.x == 0 && threadIdx.x == 0) g_ctr = 0;
    if (blockIdx.x < 8192) {
        size_t i = ((size_t)blockIdx.x * blockDim.x + threadIdx.x) * 8;
        int m = (int)(i >> 12);
        int k = (int)(i & 4095);
        float4 a = *(const float4*)(x + i);
        float4 b = *(const float4*)(x + i + 4);
        __half2 h0 = __floats2half2_rn(a.x, a.y);
        __half2 h1 = __floats2half2_rn(a.z, a.w);
        __half2 h2 = __floats2half2_rn(b.x, b.y);
        __half2 h3 = __floats2half2_rn(b.z, b.w);
        uint4 o;
        o.x = *(uint32_t*)&h0; o.y = *(uint32_t*)&h1;
        o.z = *(uint32_t*)&h2; o.w = *(uint32_t*)&h3;
        int chunk = (m >> 7) * NKIT + (k >> 6);
        uint32_t off = SWZ((uint32_t)(m & 127) * 128 + (uint32_t)((k & 63) >> 3) * 16);
        *(uint4*)((char*)g_xh + ((size_t)chunk << 14) + off) = o;
    } else {
        size_t c = ((size_t)(blockIdx.x - 8192) * blockDim.x + threadIdx.x) * 4;
        int o_row = (int)(c >> 11);
        int k0 = (int)(c & 2047) * 2;
        int4 v = *(const int4*)(wp + c);
        uint4 o;
        o.x = dq_pair(v.x); o.y = dq_pair(v.y);
        o.z = dq_pair(v.z); o.w = dq_pair(v.w);
        int chunk = (o_row >> 8) * NKIT + (k0 >> 6);          // 256-row tiles
        uint32_t off = SWZ((uint32_t)(o_row & 255) * 128 + (uint32_t)((k0 & 63) >> 3) * 16);
        *(uint4*)((char*)g_w + ((size_t)chunk << 15) + off) = o;
    }
}

// ---------------- persistent GEMM: 8 warps @ 64x64, mbarrier ring, 1 CTA/SM ----------------
__global__ __launch_bounds__(NTHREADS, 1) void k_gemm(const float* __restrict__ scale,
                                                      const float* __restrict__ bias,
                                                      float* __restrict__ out) {
    extern __shared__ __align__(1024) char smem[];
    __shared__ int s_tile;

    const int tid  = threadIdx.x;
    const int wid  = tid >> 5;
    const int lane = tid & 31;

    const int wm0 = (wid & 1) * 64;       // 2 warps in M
    const int wn0 = (wid >> 1) * 64;      // 4 warps in N
    const int lrow = lane & 15;
    const int lchk = lane >> 4;

    const uint32_t sb = smem_u32(smem);
    const uint32_t mb_full  = sb + SMEM_MBAR;        // full[s]  at +8*s
    const uint32_t mb_empty = sb + SMEM_MBAR + 32;   // empty[s] at +8*s

    // LDSM address algebra (row&7 == lrow&7 for all fragment rows)
    const uint32_t b0x = ((uint32_t)(lchk ^ (lrow & 1))) << 4;
    uint32_t baseA[4], baseB[4];
    #pragma unroll
    for (int mti = 0; mti < 4; ++mti)
        baseA[mti] = (uint32_t)(wm0 + mti * 16 + lrow) * 128 + b0x;
    #pragma unroll
    for (int np = 0; np < 4; ++np)
        baseB[np] = A_CHUNK_BYTES + (uint32_t)(wn0 + np * 16 + lrow) * 128 + b0x;
    const uint32_t kx6 = (uint32_t)(lrow & 6);

    if (tid == 0) {
        #pragma unroll
        for (int s = 0; s < STAGES; ++s) {
            MBARRIER_INIT(mb_full  + 8 * s, 1);
            MBARRIER_INIT(mb_empty + 8 * s, 8);
        }
        s_tile = atomicAdd(&g_ctr, 1);
    }
    __syncthreads();
    int t_cur = s_tile;

    int pstage = 0, pphase = 1;     // producer empty-wait cursor
    int cstage = 0, cphase = 0;     // consumer full-wait cursor

    // prologue: produce chunks 0..2 of first tile
    if (t_cur < NTILES) {
        const char* gA0 = (const char*)g_xh + ((size_t)((t_cur % MT_TILES) * NKIT) << 14);
        const char* gB0 = (const char*)g_w  + ((size_t)((t_cur / MT_TILES) * NKIT) << 15);
        #pragma unroll
        for (int c = 0; c < STAGES - 1; ++c) {
            if (tid == 0) {
                const uint32_t bar = mb_full + 8 * pstage;
                MBARRIER_EXPECT_TX(bar, STAGE_BYTES);
                CP_BULK(sb + pstage * STAGE_BYTES,                 gA0 + ((size_t)c << 14), A_CHUNK_BYTES, bar);
                CP_BULK(sb + pstage * STAGE_BYTES + A_CHUNK_BYTES, gB0 + ((size_t)c << 15), B_CHUNK_BYTES, bar);
            }
            if (++pstage == STAGES) { pstage = 0; pphase ^= 1; }
        }
    }

    while (t_cur < NTILES) {
        if (tid == 0) s_tile = atomicAdd(&g_ctr, 1);
        __syncthreads();
        const int t_next = s_tile;

        const int mt = t_cur % MT_TILES;
        const int nt = t_cur / MT_TILES;
        const int m0 = mt * BM;
        const int n0 = nt * BN;

        const char* gA_cur = (const char*)g_xh + ((size_t)(mt * NKIT) << 14);
        const char* gB_cur = (const char*)g_w  + ((size_t)(nt * NKIT) << 15);
        const char* gA_nxt = gA_cur;
        const char* gB_nxt = gB_cur;
        if (t_next < NTILES) {
            gA_nxt = (const char*)g_xh + ((size_t)((t_next % MT_TILES) * NKIT) << 14);
            gB_nxt = (const char*)g_w  + ((size_t)((t_next / MT_TILES) * NKIT) << 15);
        }

        float acc[4][8][4];
        #pragma unroll
        for (int i = 0; i < 4; ++i)
            #pragma unroll
            for (int j = 0; j < 8; ++j)
                #pragma unroll
                for (int k = 0; k < 4; ++k) acc[i][j][k] = 0.f;

        for (int it = 0; it < NKIT; ++it) {
            // ---- producer: chunk it+STAGES-1 (spills into next tile) ----
            int pc = it + STAGES - 1;
            bool have;
            const char *pa, *pb;
            if (pc < NKIT) {
                have = true;
                pa = gA_cur + ((size_t)pc << 14);
                pb = gB_cur + ((size_t)pc << 15);
            } else if (t_next < NTILES) {
                have = true;
                pa = gA_nxt + ((size_t)(pc - NKIT) << 14);
                pb = gB_nxt + ((size_t)(pc - NKIT) << 15);
            } else {
                have = false; pa = pb = nullptr;
            }
            if (have) {
                if (tid == 0) {
                    MBARRIER_WAIT_PARITY(mb_empty + 8 * pstage, (uint32_t)pphase);
                    const uint32_t bar = mb_full + 8 * pstage;
                    MBARRIER_EXPECT_TX(bar, STAGE_BYTES);
                    CP_BULK(sb + pstage * STAGE_BYTES,                 pa, A_CHUNK_BYTES, bar);
                    CP_BULK(sb + pstage * STAGE_BYTES + A_CHUNK_BYTES, pb, B_CHUNK_BYTES, bar);
                }
                if (++pstage == STAGES) { pstage = 0; pphase ^= 1; }
            }

            // ---- consumer ----
            MBARRIER_WAIT_PARITY(mb_full + 8 * cstage, (uint32_t)cphase);
            const uint32_t sA = sb + cstage * STAGE_BYTES;
            #pragma unroll
            for (int ks = 0; ks < 4; ++ks) {
                const uint32_t kbase = sA + ((((uint32_t)(2 * ks)) ^ kx6) << 4);
                uint32_t a[4][4];
                #pragma unroll
                for (int mti = 0; mti < 4; ++mti)
                    LDSM_X4(a[mti][0], a[mti][1], a[mti][2], a[mti][3],
                            kbase + baseA[mti]);
                uint32_t b[8][2];
                #pragma unroll
                for (int np = 0; np < 4; ++np) {
                    uint32_t r0, r1, r2, r3;
                    LDSM_X4(r0, r1, r2, r3, kbase + baseB[np]);
                    b[2 * np + 0][0] = r0; b[2 * np + 0][1] = r2;
                    b[2 * np + 1][0] = r1; b[2 * np + 1][1] = r3;
                }
                #pragma unroll
                for (int mti = 0; mti < 4; ++mti)
                    #pragma unroll
                    for (int nti = 0; nti < 8; ++nti)
                        MMA16816(acc[mti][nti], a[mti], b[nti]);
            }
            if (lane == 0) MBARRIER_ARRIVE(mb_empty + 8 * cstage);
            if (++cstage == STAGES) { cstage = 0; cphase ^= 1; }
        }

        // ---------------- epilogue (overlaps next tile's TMA) ----------------
        {
            const int row_base = m0 + wm0;
            const int col_base = n0 + wn0;
            const int r_in = lane >> 2;
            const int c_in = (lane & 3) * 2;

            #pragma unroll
            for (int nti = 0; nti < 8; ++nti) {
                const int c = col_base + nti * 8 + c_in;
                const float2 sc = *(const float2*)(scale + c);
                const float2 bi = *(const float2*)(bias + c);
                #pragma unroll
                for (int mti = 0; mti < 4; ++mti) {
                    const int r0 = row_base + mti * 16 + r_in;
                    float2 v0, v1;
                    v0.x = acc[mti][nti][0] * sc.x + bi.x;
                    v0.y = acc[mti][nti][1] * sc.y + bi.y;
                    v1.x = acc[mti][nti][2] * sc.x + bi.x;
                    v1.y = acc[mti][nti][3] * sc.y + bi.y;
                    *(float2*)(out + (size_t)r0 * N_TOTAL + c)       = v0;
                    *(float2*)(out + (size_t)(r0 + 8) * N_TOTAL + c) = v1;
                }
            }
        }

        t_cur = t_next;
    }
}

// ---------------- launch ----------------
extern "C" void kernel_launch(void* const* d_in, const int* in_sizes, int n_in,
                              void* d_out, int out_size) {
    const float* x   = (const float*)d_in[0];
    const int*   wp  = (const int*)d_in[1];
    const float* scl = (const float*)d_in[2];
    const float* bia = (const float*)d_in[3];
    float* out = (float*)d_out;

    cudaFuncSetAttribute(k_gemm, cudaFuncAttributeMaxDynamicSharedMemorySize, SMEM_BYTES);

    // fused prep: tile-major, pre-swizzled (A: 128-row tiles, W: 256-row tiles)
    k_prep<<<30208, 256>>>(x, wp);
    // persistent GEMM, 1 CTA/SM, 64x64 warp tiles, continuous ring pipeline
    k_gemm<<<148, NTHREADS, SMEM_BYTES>>>(scl, bia, out);
}

// round 13
// speedup vs baseline: 1.0358x; 1.0358x over previous
#include <cuda_runtime.h>
#include <cuda_fp16.h>
#include <cstdint>

// ---------------- problem constants ----------------
#define M_TOTAL   4096
#define K_TOTAL   4096
#define N_TOTAL   11008

#define BM        128
#define BN        128
#define BK        64                  // fp16 per K chunk (128 B/row)
#define NKIT      (K_TOTAL / BK)      // 64
#define MT_TILES  (M_TOTAL / BM)      // 32
#define NT_TILES  (N_TOTAL / BN)      // 86
#define NTILES    (MT_TILES * NT_TILES)  // 2752
#define STAGES    3
#define NTHREADS  256

#define CHUNK_BYTES   16384                             // one (tile,kc) block, pre-swizzled
#define A_STAGE_BYTES CHUNK_BYTES
#define STAGE_BYTES   (2 * CHUNK_BYTES)                 // A + B = 32768
#define SMEM_DATA     (STAGES * STAGE_BYTES)            // 98304
#define SMEM_MBAR     SMEM_DATA                         // full[3] then empty[3]
#define SMEM_BYTES    (SMEM_DATA + 64)

// ---------------- device scratch (tile-major, pre-swizzled) ----------------
static __device__ __align__(16) __half g_xh[(size_t)M_TOTAL * K_TOTAL];   // ~34 MB
static __device__ __align__(16) __half g_w [(size_t)N_TOTAL * K_TOTAL];   // ~90 MB
static __device__ int g_ctr;

// ---------------- helpers ----------------
#define SWZ(off) ((off) ^ (((off) >> 3) & 0x70))

__device__ __forceinline__ uint32_t smem_u32(const void* p) {
    uint32_t a;
    asm("{ .reg .u64 t; cvta.to.shared.u64 t, %1; cvt.u32.u64 %0, t; }" : "=r"(a) : "l"(p));
    return a;
}

#define CP_BULK(dst_u32, src_ptr, bytes, mbar_u32) \
    asm volatile("cp.async.bulk.shared::cluster.global.mbarrier::complete_tx::bytes " \
                 "[%0], [%1], %2, [%3];" \
                 :: "r"(dst_u32), "l"(src_ptr), "r"(bytes), "r"(mbar_u32) : "memory")

#define MBARRIER_INIT(mbar, cnt) \
    asm volatile("mbarrier.init.shared.b64 [%0], %1;" \
                 :: "r"((uint32_t)(mbar)), "r"((uint32_t)(cnt)) : "memory")
#define MBARRIER_EXPECT_TX(mbar, tx) \
    asm volatile("mbarrier.arrive.expect_tx.shared.b64 _, [%0], %1;" \
                 :: "r"((uint32_t)(mbar)), "r"((uint32_t)(tx)) : "memory")
#define MBARRIER_ARRIVE(mbar) \
    asm volatile("mbarrier.arrive.shared.b64 _, [%0];" \
                 :: "r"((uint32_t)(mbar)) : "memory")

#define MBARRIER_WAIT_PARITY(mbar_smem_addr, phase_parity) do { \
    uint32_t _mbar = (uint32_t)(mbar_smem_addr); \
    uint32_t _parity = (uint32_t)(phase_parity); \
    uint32_t _done; \
    asm volatile( \
        "{\n\t.reg .pred p;\n\t" \
        "mbarrier.try_wait.parity.acquire.cta.shared::cta.b64 p, [%1], %2;\n\t" \
        "selp.b32 %0, 1, 0, p;\n\t}" \
        : "=r"(_done) : "r"(_mbar), "r"(_parity) : "memory"); \
    if (!_done) { \
        asm volatile( \
            "{\n\t.reg .pred P1;\n\t" \
            "WAIT_LOOP_%=:\n\t" \
            "mbarrier.try_wait.parity.acquire.cta.shared::cta.b64 P1, [%0], %1, 0x989680;\n\t" \
            "@P1 bra.uni WAIT_DONE_%=;\n\t" \
            "bra.uni WAIT_LOOP_%=;\n\t" \
            "WAIT_DONE_%=:\n\t}" \
            :: "r"(_mbar), "r"(_parity) : "memory"); \
    } \
} while (0)

#define LDSM_X4(r0, r1, r2, r3, addr) \
    asm volatile("ldmatrix.sync.aligned.m8n8.x4.shared.b16 {%0,%1,%2,%3}, [%4];" \
                 : "=r"(r0), "=r"(r1), "=r"(r2), "=r"(r3) : "r"(addr))

#define MMA16816(c, a, b) \
    asm volatile("mma.sync.aligned.m16n8k16.row.col.f32.f16.f16.f32 " \
                 "{%0,%1,%2,%3}, {%4,%5,%6,%7}, {%8,%9}, {%0,%1,%2,%3};" \
                 : "+f"((c)[0]), "+f"((c)[1]), "+f"((c)[2]), "+f"((c)[3]) \
                 : "r"((a)[0]), "r"((a)[1]), "r"((a)[2]), "r"((a)[3]), \
                   "r"((b)[0]), "r"((b)[1]))

// ---------------- fused prep kernel: tile-major pre-swizzled outputs ----------------
__device__ __forceinline__ uint32_t dq_pair(int v) {
    int lo = (v & 15) - 8;
    int hi = ((v >> 4) & 15) - 8;
    __half2 h = __floats2half2_rn((float)lo, (float)hi);
    return *(uint32_t*)&h;
}

__global__ void k_prep(const float* __restrict__ x, const int* __restrict__ wp) {
    if (blockIdx.x == 0 && threadIdx.x == 0) g_ctr = 0;
    if (blockIdx.x < 8192) {
        size_t i = ((size_t)blockIdx.x * blockDim.x + threadIdx.x) * 8;
        int m = (int)(i >> 12);
        int k = (int)(i & 4095);
        float4 a = *(const float4*)(x + i);
        float4 b = *(const float4*)(x + i + 4);
        __half2 h0 = __floats2half2_rn(a.x, a.y);
        __half2 h1 = __floats2half2_rn(a.z, a.w);
        __half2 h2 = __floats2half2_rn(b.x, b.y);
        __half2 h3 = __floats2half2_rn(b.z, b.w);
        uint4 o;
        o.x = *(uint32_t*)&h0; o.y = *(uint32_t*)&h1;
        o.z = *(uint32_t*)&h2; o.w = *(uint32_t*)&h3;
        int chunk = (m >> 7) * NKIT + (k >> 6);
        uint32_t off = SWZ((uint32_t)(m & 127) * 128 + (uint32_t)((k & 63) >> 3) * 16);
        *(uint4*)((char*)g_xh + ((size_t)chunk << 14) + off) = o;
    } else {
        size_t c = ((size_t)(blockIdx.x - 8192) * blockDim.x + threadIdx.x) * 4;
        int o_row = (int)(c >> 11);
        int k0 = (int)(c & 2047) * 2;
        int4 v = *(const int4*)(wp + c);
        uint4 o;
        o.x = dq_pair(v.x); o.y = dq_pair(v.y);
        o.z = dq_pair(v.z); o.w = dq_pair(v.w);
        int chunk = (o_row >> 7) * NKIT + (k0 >> 6);
        uint32_t off = SWZ((uint32_t)(o_row & 127) * 128 + (uint32_t)((k0 & 63) >> 3) * 16);
        *(uint4*)((char*)g_w + ((size_t)chunk << 14) + off) = o;
    }
}

// ---------------- persistent GEMM: mbarrier ring + A-fragment double buffer ----------------
__global__ __launch_bounds__(NTHREADS, 2) void k_gemm(const float* __restrict__ scale,
                                                      const float* __restrict__ bias,
                                                      float* __restrict__ out) {
    extern __shared__ __align__(1024) char smem[];
    __shared__ int s_tile;

    const int tid  = threadIdx.x;
    const int wid  = tid >> 5;
    const int lane = tid & 31;

    const int wm0 = (wid & 1) * 64;
    const int wn0 = (wid >> 1) * 32;

    const uint32_t sb = smem_u32(smem);
    const uint32_t mb_full  = sb + SMEM_MBAR;        // full[s]  at +8*s
    const uint32_t mb_empty = sb + SMEM_MBAR + 24;   // empty[s] at +8*s
    const int lrow = lane & 15;
    const int lchk = lane >> 4;

    // LDSM address algebra (row&7 == lrow&7 for all fragment rows)
    const uint32_t b0x = ((uint32_t)(lchk ^ (lrow & 1))) << 4;
    uint32_t baseA[4], baseB[2];
    #pragma unroll
    for (int mti = 0; mti < 4; ++mti)
        baseA[mti] = (uint32_t)(wm0 + mti * 16 + lrow) * 128 + b0x;
    #pragma unroll
    for (int np = 0; np < 2; ++np)
        baseB[np] = A_STAGE_BYTES + (uint32_t)(wn0 + np * 16 + lrow) * 128 + b0x;
    const uint32_t kx6 = (uint32_t)(lrow & 6);

    if (tid == 0) {
        #pragma unroll
        for (int s = 0; s < STAGES; ++s) {
            MBARRIER_INIT(mb_full  + 8 * s, 1);
            MBARRIER_INIT(mb_empty + 8 * s, 8);
        }
        s_tile = atomicAdd(&g_ctr, 1);
    }
    __syncthreads();
    int t_cur = s_tile;

    int pstage = 0, pphase = 1;
    int cstage = 0, cphase = 0;

    if (t_cur < NTILES) {
        const char* gA0 = (const char*)g_xh + ((size_t)((t_cur % MT_TILES) * NKIT) << 14);
        const char* gB0 = (const char*)g_w  + ((size_t)((t_cur / MT_TILES) * NKIT) << 14);
        #pragma unroll
        for (int c = 0; c < 2; ++c) {
            if (tid == 0) {
                const uint32_t bar = mb_full + 8 * pstage;
                MBARRIER_EXPECT_TX(bar, STAGE_BYTES);
                CP_BULK(sb + pstage * STAGE_BYTES,                 gA0 + ((size_t)c << 14), CHUNK_BYTES, bar);
                CP_BULK(sb + pstage * STAGE_BYTES + A_STAGE_BYTES, gB0 + ((size_t)c << 14), CHUNK_BYTES, bar);
            }
            if (++pstage == STAGES) { pstage = 0; pphase ^= 1; }
        }
    }

    while (t_cur < NTILES) {
        if (tid == 0) s_tile = atomicAdd(&g_ctr, 1);
        __syncthreads();
        const int t_next = s_tile;

        const int mt = t_cur % MT_TILES;
        const int nt = t_cur / MT_TILES;
        const int m0 = mt * BM;
        const int n0 = nt * BN;

        const char* gA_cur = (const char*)g_xh + ((size_t)(mt * NKIT) << 14);
        const char* gB_cur = (const char*)g_w  + ((size_t)(nt * NKIT) << 14);
        const char* gA_nxt = gA_cur;
        const char* gB_nxt = gB_cur;
        if (t_next < NTILES) {
            gA_nxt = (const char*)g_xh + ((size_t)((t_next % MT_TILES) * NKIT) << 14);
            gB_nxt = (const char*)g_w  + ((size_t)((t_next / MT_TILES) * NKIT) << 14);
        }

        float acc[4][4][4];
        #pragma unroll
        for (int i = 0; i < 4; ++i)
            #pragma unroll
            for (int j = 0; j < 4; ++j)
                #pragma unroll
                for (int k = 0; k < 4; ++k) acc[i][j][k] = 0.f;

        for (int it = 0; it < NKIT; ++it) {
            // ---- producer: chunk it+2 (spills into next tile's chunks 0,1) ----
            int pc = it + 2;
            bool have;
            const char *pa, *pb;
            if (pc < NKIT) {
                have = true;
                pa = gA_cur + ((size_t)pc << 14);
                pb = gB_cur + ((size_t)pc << 14);
            } else if (t_next < NTILES) {
                have = true;
                pa = gA_nxt + ((size_t)(pc - NKIT) << 14);
                pb = gB_nxt + ((size_t)(pc - NKIT) << 14);
            } else {
                have = false; pa = pb = nullptr;
            }
            if (have) {
                if (tid == 0) {
                    MBARRIER_WAIT_PARITY(mb_empty + 8 * pstage, (uint32_t)pphase);
                    const uint32_t bar = mb_full + 8 * pstage;
                    MBARRIER_EXPECT_TX(bar, STAGE_BYTES);
                    CP_BULK(sb + pstage * STAGE_BYTES,                 pa, CHUNK_BYTES, bar);
                    CP_BULK(sb + pstage * STAGE_BYTES + A_STAGE_BYTES, pb, CHUNK_BYTES, bar);
                }
                if (++pstage == STAGES) { pstage = 0; pphase ^= 1; }
            }

            // ---- consumer: stage cstage, A fragments double-buffered across ks ----
            MBARRIER_WAIT_PARITY(mb_full + 8 * cstage, (uint32_t)cphase);
            const uint32_t sA = sb + cstage * STAGE_BYTES;

            uint32_t afr[2][4][4];
            {   // preload A for ks=0
                const uint32_t kb0 = sA + ((0u ^ kx6) << 4);
                #pragma unroll
                for (int mti = 0; mti < 4; ++mti)
                    LDSM_X4(afr[0][mti][0], afr[0][mti][1], afr[0][mti][2], afr[0][mti][3],
                            kb0 + baseA[mti]);
            }

            #pragma unroll
            for (int ks = 0; ks < 4; ++ks) {
                const int cur = ks & 1;
                const uint32_t kbase = sA + ((((uint32_t)(2 * ks)) ^ kx6) << 4);

                // B fragments for this ks
                uint32_t b[4][2];
                #pragma unroll
                for (int np = 0; np < 2; ++np) {
                    uint32_t r0, r1, r2, r3;
                    LDSM_X4(r0, r1, r2, r3, kbase + baseB[np]);
                    b[2 * np + 0][0] = r0; b[2 * np + 0][1] = r2;
                    b[2 * np + 1][0] = r1; b[2 * np + 1][1] = r3;
                }
                // prefetch A for ks+1 (hides LDSM latency under this ks's MMAs)
                if (ks < 3) {
                    const uint32_t kbn = sA + ((((uint32_t)(2 * (ks + 1))) ^ kx6) << 4);
                    #pragma unroll
                    for (int mti = 0; mti < 4; ++mti)
                        LDSM_X4(afr[cur ^ 1][mti][0], afr[cur ^ 1][mti][1],
                                afr[cur ^ 1][mti][2], afr[cur ^ 1][mti][3],
                                kbn + baseA[mti]);
                }
                #pragma unroll
                for (int mti = 0; mti < 4; ++mti)
                    #pragma unroll
                    for (int nti = 0; nti < 4; ++nti)
                        MMA16816(acc[mti][nti], afr[cur][mti], b[nti]);
            }
            if (lane == 0) MBARRIER_ARRIVE(mb_empty + 8 * cstage);
            if (++cstage == STAGES) { cstage = 0; cphase ^= 1; }
        }

        // ---------------- epilogue (overlaps next tile's TMA) ----------------
        {
            const int row_base = m0 + wm0;
            const int col_base = n0 + wn0;
            const int r_in = lane >> 2;
            const int c_in = (lane & 3) * 2;

            #pragma unroll
            for (int nti = 0; nti < 4; ++nti) {
                const int c = col_base + nti * 8 + c_in;
                const float2 sc = *(const float2*)(scale + c);
                const float2 bi = *(const float2*)(bias + c);
                #pragma unroll
                for (int mti = 0; mti < 4; ++mti) {
                    const int r0 = row_base + mti * 16 + r_in;
                    float2 v0, v1;
                    v0.x = acc[mti][nti][0] * sc.x + bi.x;
                    v0.y = acc[mti][nti][1] * sc.y + bi.y;
                    v1.x = acc[mti][nti][2] * sc.x + bi.x;
                    v1.y = acc[mti][nti][3] * sc.y + bi.y;
                    *(float2*)(out + (size_t)r0 * N_TOTAL + c)       = v0;
                    *(float2*)(out + (size_t)(r0 + 8) * N_TOTAL + c) = v1;
                }
            }
        }

        t_cur = t_next;
    }
}

// ---------------- launch ----------------
extern "C" void kernel_launch(void* const* d_in, const int* in_sizes, int n_in,
                              void* d_out, int out_size) {
    const float* x   = (const float*)d_in[0];
    const int*   wp  = (const int*)d_in[1];
    const float* scl = (const float*)d_in[2];
    const float* bia = (const float*)d_in[3];
    float* out = (float*)d_out;

    cudaFuncSetAttribute(k_gemm, cudaFuncAttributeMaxDynamicSharedMemorySize, SMEM_BYTES);

    // fused prep: tile-major, pre-swizzled
    k_prep<<<30208, 256>>>(x, wp);
    // persistent GEMM, 2 CTAs/SM, continuous ring + A-fragment pipelining
    k_gemm<<<296, NTHREADS, SMEM_BYTES>>>(scl, bia, out);
}

// round 14
// speedup vs baseline: 1.1937x; 1.1525x over previous
#include <cuda_runtime.h>
#include <cuda_fp16.h>
#include <cstdint>

// ---------------- problem constants ----------------
#define M_TOTAL   4096
#define K_TOTAL   4096
#define N_TOTAL   11008

#define BM        128
#define BN        128
#define BK        64                  // fp16 per K chunk (128 B/row)
#define NKIT      (K_TOTAL / BK)      // 64
#define MT_TILES  (M_TOTAL / BM)      // 32
#define NT_TILES  (N_TOTAL / BN)      // 86
#define NTILES    (MT_TILES * NT_TILES)  // 2752
#define STAGES    3
#define NTHREADS  256

#define CHUNK_BYTES   16384                             // one (tile,kc) block, pre-swizzled
#define A_STAGE_BYTES CHUNK_BYTES
#define STAGE_BYTES   (2 * CHUNK_BYTES)                 // A + B = 32768
#define SMEM_DATA     (STAGES * STAGE_BYTES)            // 98304
#define SMEM_MBAR     SMEM_DATA                         // full[3] then empty[3]
#define SMEM_BYTES    (SMEM_DATA + 64)

// ---------------- device scratch (tile-major, pre-swizzled) ----------------
static __device__ __align__(16) __half g_xh[(size_t)M_TOTAL * K_TOTAL];   // ~34 MB
static __device__ __align__(16) __half g_w [(size_t)N_TOTAL * K_TOTAL];   // ~90 MB
static __device__ int g_ctr;

// ---------------- helpers ----------------
#define SWZ(off) ((off) ^ (((off) >> 3) & 0x70))

__device__ __forceinline__ uint32_t smem_u32(const void* p) {
    uint32_t a;
    asm("{ .reg .u64 t; cvta.to.shared.u64 t, %1; cvt.u32.u64 %0, t; }" : "=r"(a) : "l"(p));
    return a;
}

#define CP_BULK(dst_u32, src_ptr, bytes, mbar_u32) \
    asm volatile("cp.async.bulk.shared::cluster.global.mbarrier::complete_tx::bytes " \
                 "[%0], [%1], %2, [%3];" \
                 :: "r"(dst_u32), "l"(src_ptr), "r"(bytes), "r"(mbar_u32) : "memory")

#define MBARRIER_INIT(mbar, cnt) \
    asm volatile("mbarrier.init.shared.b64 [%0], %1;" \
                 :: "r"((uint32_t)(mbar)), "r"((uint32_t)(cnt)) : "memory")
#define MBARRIER_EXPECT_TX(mbar, tx) \
    asm volatile("mbarrier.arrive.expect_tx.shared.b64 _, [%0], %1;" \
                 :: "r"((uint32_t)(mbar)), "r"((uint32_t)(tx)) : "memory")
#define MBARRIER_ARRIVE(mbar) \
    asm volatile("mbarrier.arrive.shared.b64 _, [%0];" \
                 :: "r"((uint32_t)(mbar)) : "memory")

#define MBARRIER_WAIT_PARITY(mbar_smem_addr, phase_parity) do { \
    uint32_t _mbar = (uint32_t)(mbar_smem_addr); \
    uint32_t _parity = (uint32_t)(phase_parity); \
    uint32_t _done; \
    asm volatile( \
        "{\n\t.reg .pred p;\n\t" \
        "mbarrier.try_wait.parity.acquire.cta.shared::cta.b64 p, [%1], %2;\n\t" \
        "selp.b32 %0, 1, 0, p;\n\t}" \
        : "=r"(_done) : "r"(_mbar), "r"(_parity) : "memory"); \
    if (!_done) { \
        asm volatile( \
            "{\n\t.reg .pred P1;\n\t" \
            "WAIT_LOOP_%=:\n\t" \
            "mbarrier.try_wait.parity.acquire.cta.shared::cta.b64 P1, [%0], %1, 0x989680;\n\t" \
            "@P1 bra.uni WAIT_DONE_%=;\n\t" \
            "bra.uni WAIT_LOOP_%=;\n\t" \
            "WAIT_DONE_%=:\n\t}" \
            :: "r"(_mbar), "r"(_parity) : "memory"); \
    } \
} while (0)

#define LDSM_X4(r0, r1, r2, r3, addr) \
    asm volatile("ldmatrix.sync.aligned.m8n8.x4.shared.b16 {%0,%1,%2,%3}, [%4];" \
                 : "=r"(r0), "=r"(r1), "=r"(r2), "=r"(r3) : "r"(addr))

#define MMA16816(c, a, b) \
    asm volatile("mma.sync.aligned.m16n8k16.row.col.f32.f16.f16.f32 " \
                 "{%0,%1,%2,%3}, {%4,%5,%6,%7}, {%8,%9}, {%0,%1,%2,%3};" \
                 : "+f"((c)[0]), "+f"((c)[1]), "+f"((c)[2]), "+f"((c)[3]) \
                 : "r"((a)[0]), "r"((a)[1]), "r"((a)[2]), "r"((a)[3]), \
                   "r"((b)[0]), "r"((b)[1]))

// ---------------- fused prep kernel: tile-major pre-swizzled outputs ----------------
__device__ __forceinline__ uint32_t dq_pair(int v) {
    int lo = (v & 15) - 8;
    int hi = ((v >> 4) & 15) - 8;
    __half2 h = __floats2half2_rn((float)lo, (float)hi);
    return *(uint32_t*)&h;
}

__global__ void k_prep(const float* __restrict__ x, const int* __restrict__ wp) {
    if (blockIdx.x == 0 && threadIdx.x == 0) g_ctr = 0;
    if (blockIdx.x < 8192) {
        size_t i = ((size_t)blockIdx.x * blockDim.x + threadIdx.x) * 8;
        int m = (int)(i >> 12);
        int k = (int)(i & 4095);
        float4 a = *(const float4*)(x + i);
        float4 b = *(const float4*)(x + i + 4);
        __half2 h0 = __floats2half2_rn(a.x, a.y);
        __half2 h1 = __floats2half2_rn(a.z, a.w);
        __half2 h2 = __floats2half2_rn(b.x, b.y);
        __half2 h3 = __floats2half2_rn(b.z, b.w);
        uint4 o;
        o.x = *(uint32_t*)&h0; o.y = *(uint32_t*)&h1;
        o.z = *(uint32_t*)&h2; o.w = *(uint32_t*)&h3;
        int chunk = (m >> 7) * NKIT + (k >> 6);
        uint32_t off = SWZ((uint32_t)(m & 127) * 128 + (uint32_t)((k & 63) >> 3) * 16);
        *(uint4*)((char*)g_xh + ((size_t)chunk << 14) + off) = o;
    } else {
        size_t c = ((size_t)(blockIdx.x - 8192) * blockDim.x + threadIdx.x) * 4;
        int o_row = (int)(c >> 11);
        int k0 = (int)(c & 2047) * 2;
        int4 v = *(const int4*)(wp + c);
        uint4 o;
        o.x = dq_pair(v.x); o.y = dq_pair(v.y);
        o.z = dq_pair(v.z); o.w = dq_pair(v.w);
        int chunk = (o_row >> 7) * NKIT + (k0 >> 6);
        uint32_t off = SWZ((uint32_t)(o_row & 127) * 128 + (uint32_t)((k0 & 63) >> 3) * 16);
        *(uint4*)((char*)g_w + ((size_t)chunk << 14) + off) = o;
    }
}

// ---------------- persistent GEMM: ring + fully pipelined A/B fragments ----------------
__global__ __launch_bounds__(NTHREADS, 2) void k_gemm(const float* __restrict__ scale,
                                                      const float* __restrict__ bias,
                                                      float* __restrict__ out) {
    extern __shared__ __align__(1024) char smem[];
    __shared__ int s_tile;

    const int tid  = threadIdx.x;
    const int wid  = tid >> 5;
    const int lane = tid & 31;

    const int wm0 = (wid & 1) * 64;
    const int wn0 = (wid >> 1) * 32;

    const uint32_t sb = smem_u32(smem);
    const uint32_t mb_full  = sb + SMEM_MBAR;        // full[s]  at +8*s
    const uint32_t mb_empty = sb + SMEM_MBAR + 24;   // empty[s] at +8*s
    const int lrow = lane & 15;
    const int lchk = lane >> 4;

    // LDSM address algebra (row&7 == lrow&7 for all fragment rows)
    const uint32_t b0x = ((uint32_t)(lchk ^ (lrow & 1))) << 4;
    uint32_t baseA[4], baseB[2];
    #pragma unroll
    for (int mti = 0; mti < 4; ++mti)
        baseA[mti] = (uint32_t)(wm0 + mti * 16 + lrow) * 128 + b0x;
    #pragma unroll
    for (int np = 0; np < 2; ++np)
        baseB[np] = A_STAGE_BYTES + (uint32_t)(wn0 + np * 16 + lrow) * 128 + b0x;
    const uint32_t kx6 = (uint32_t)(lrow & 6);

    if (tid == 0) {
        #pragma unroll
        for (int s = 0; s < STAGES; ++s) {
            MBARRIER_INIT(mb_full  + 8 * s, 1);
            MBARRIER_INIT(mb_empty + 8 * s, 8);
        }
        s_tile = atomicAdd(&g_ctr, 1);
    }
    __syncthreads();
    int t_cur = s_tile;

    int pstage = 0, pphase = 1;
    int cstage = 0, cphase = 0;

    // fragment buffers (double-buffered across ks, persisted across iters/tiles)
    uint32_t afr[2][4][4];
    uint32_t bfr[2][2][4];   // bfr[buf][np][r0..r3] raw ldmatrix regs

    auto load_frags = [&](uint32_t stage_base, int ks, int buf) {
        const uint32_t kbase = stage_base + ((((uint32_t)(2 * ks)) ^ kx6) << 4);
        #pragma unroll
        for (int mti = 0; mti < 4; ++mti)
            LDSM_X4(afr[buf][mti][0], afr[buf][mti][1], afr[buf][mti][2], afr[buf][mti][3],
                    kbase + baseA[mti]);
        #pragma unroll
        for (int np = 0; np < 2; ++np)
            LDSM_X4(bfr[buf][np][0], bfr[buf][np][1], bfr[buf][np][2], bfr[buf][np][3],
                    kbase + baseB[np]);
    };

    auto mma_block = [&](float (&acc)[4][4][4], int buf) {
        #pragma unroll
        for (int mti = 0; mti < 4; ++mti) {
            #pragma unroll
            for (int np = 0; np < 2; ++np) {
                uint32_t b0[2] = { bfr[buf][np][0], bfr[buf][np][2] };
                uint32_t b1[2] = { bfr[buf][np][1], bfr[buf][np][3] };
                MMA16816(acc[mti][2 * np + 0], afr[buf][mti], b0);
                MMA16816(acc[mti][2 * np + 1], afr[buf][mti], b1);
            }
        }
    };

    // prologue: produce chunks 0,1 of first tile
    if (t_cur < NTILES) {
        const char* gA0 = (const char*)g_xh + ((size_t)((t_cur % MT_TILES) * NKIT) << 14);
        const char* gB0 = (const char*)g_w  + ((size_t)((t_cur / MT_TILES) * NKIT) << 14);
        #pragma unroll
        for (int c = 0; c < 2; ++c) {
            if (tid == 0) {
                const uint32_t bar = mb_full + 8 * pstage;
                MBARRIER_EXPECT_TX(bar, STAGE_BYTES);
                CP_BULK(sb + pstage * STAGE_BYTES,                 gA0 + ((size_t)c << 14), CHUNK_BYTES, bar);
                CP_BULK(sb + pstage * STAGE_BYTES + A_STAGE_BYTES, gB0 + ((size_t)c << 14), CHUNK_BYTES, bar);
            }
            if (++pstage == STAGES) { pstage = 0; pphase ^= 1; }
        }
        // prime: wait stage 0 full, load its ks=0 fragments into buf 0
        MBARRIER_WAIT_PARITY(mb_full + 8 * cstage, (uint32_t)cphase);
        load_frags(sb + cstage * STAGE_BYTES, 0, 0);
    }

    while (t_cur < NTILES) {
        if (tid == 0) s_tile = atomicAdd(&g_ctr, 1);
        __syncthreads();
        const int t_next = s_tile;

        const int mt = t_cur % MT_TILES;
        const int nt = t_cur / MT_TILES;
        const int m0 = mt * BM;
        const int n0 = nt * BN;

        const char* gA_cur = (const char*)g_xh + ((size_t)(mt * NKIT) << 14);
        const char* gB_cur = (const char*)g_w  + ((size_t)(nt * NKIT) << 14);
        const char* gA_nxt = gA_cur;
        const char* gB_nxt = gB_cur;
        if (t_next < NTILES) {
            gA_nxt = (const char*)g_xh + ((size_t)((t_next % MT_TILES) * NKIT) << 14);
            gB_nxt = (const char*)g_w  + ((size_t)((t_next / MT_TILES) * NKIT) << 14);
        }

        float acc[4][4][4];
        #pragma unroll
        for (int i = 0; i < 4; ++i)
            #pragma unroll
            for (int j = 0; j < 4; ++j)
                #pragma unroll
                for (int k = 0; k < 4; ++k) acc[i][j][k] = 0.f;

        for (int it = 0; it < NKIT; ++it) {
            // ---- producer: chunk it+2 (spills into next tile's chunks 0,1) ----
            int pc = it + 2;
            bool have;
            const char *pa, *pb;
            if (pc < NKIT) {
                have = true;
                pa = gA_cur + ((size_t)pc << 14);
                pb = gB_cur + ((size_t)pc << 14);
            } else if (t_next < NTILES) {
                have = true;
                pa = gA_nxt + ((size_t)(pc - NKIT) << 14);
                pb = gB_nxt + ((size_t)(pc - NKIT) << 14);
            } else {
                have = false; pa = pb = nullptr;
            }
            if (have) {
                if (tid == 0) {
                    MBARRIER_WAIT_PARITY(mb_empty + 8 * pstage, (uint32_t)pphase);
                    const uint32_t bar = mb_full + 8 * pstage;
                    MBARRIER_EXPECT_TX(bar, STAGE_BYTES);
                    CP_BULK(sb + pstage * STAGE_BYTES,                 pa, CHUNK_BYTES, bar);
                    CP_BULK(sb + pstage * STAGE_BYTES + A_STAGE_BYTES, pb, CHUNK_BYTES, bar);
                }
                if (++pstage == STAGES) { pstage = 0; pphase ^= 1; }
            }

            // ---- consumer: stage cstage; ks=0 frags already resident in buf0 ----
            const uint32_t sA = sb + cstage * STAGE_BYTES;

            #pragma unroll
            for (int ks = 0; ks < 3; ++ks) {
                const int cur = ks & 1;
                load_frags(sA, ks + 1, cur ^ 1);    // prefetch next ks
                mma_block(acc, cur);
            }
            // ks = 3: MMAs first, then cross-stage prefetch of next ks=0
            mma_block(acc, 1);
            {
                const bool last_global = (it == NKIT - 1) && (t_next >= NTILES);
                if (!last_global) {
                    int ns = cstage + 1, np2 = cphase;
                    if (ns == STAGES) { ns = 0; np2 ^= 1; }
                    MBARRIER_WAIT_PARITY(mb_full + 8 * ns, (uint32_t)np2);
                    load_frags(sb + ns * STAGE_BYTES, 0, 0);
                }
            }
            if (lane == 0) MBARRIER_ARRIVE(mb_empty + 8 * cstage);
            if (++cstage == STAGES) { cstage = 0; cphase ^= 1; }
        }

        // ---------------- epilogue (overlaps next tile's TMA) ----------------
        {
            const int row_base = m0 + wm0;
            const int col_base = n0 + wn0;
            const int r_in = lane >> 2;
            const int c_in = (lane & 3) * 2;

            #pragma unroll
            for (int nti = 0; nti < 4; ++nti) {
                const int c = col_base + nti * 8 + c_in;
                const float2 sc = *(const float2*)(scale + c);
                const float2 bi = *(const float2*)(bias + c);
                #pragma unroll
                for (int mti = 0; mti < 4; ++mti) {
                    const int r0 = row_base + mti * 16 + r_in;
                    float2 v0, v1;
                    v0.x = acc[mti][nti][0] * sc.x + bi.x;
                    v0.y = acc[mti][nti][1] * sc.y + bi.y;
                    v1.x = acc[mti][nti][2] * sc.x + bi.x;
                    v1.y = acc[mti][nti][3] * sc.y + bi.y;
                    *(float2*)(out + (size_t)r0 * N_TOTAL + c)       = v0;
                    *(float2*)(out + (size_t)(r0 + 8) * N_TOTAL + c) = v1;
                }
            }
        }

        t_cur = t_next;
    }
}

// ---------------- launch ----------------
extern "C" void kernel_launch(void* const* d_in, const int* in_sizes, int n_in,
                              void* d_out, int out_size) {
    const float* x   = (const float*)d_in[0];
    const int*   wp  = (const int*)d_in[1];
    const float* scl = (const float*)d_in[2];
    const float* bia = (const float*)d_in[3];
    float* out = (float*)d_out;

    cudaFuncSetAttribute(k_gemm, cudaFuncAttributeMaxDynamicSharedMemorySize, SMEM_BYTES);

    // fused prep: tile-major, pre-swizzled
    k_prep<<<30208, 256>>>(x, wp);
    // persistent GEMM, 2 CTAs/SM, ring + full fragment pipeline
    k_gemm<<<296, NTHREADS, SMEM_BYTES>>>(scl, bia, out);
}